// round 13
// baseline (speedup 1.0000x reference)
#include <cuda_runtime.h>
#include <cstdint>

#define T_STEPS 96
#define BATCH   32
#define HDIM    512
#define NCP     82
#define NBP     226
#define FEAT    2048
#define NBLK    128
#define LOG2E   1.4426950408889634f

#define OFF_OC 0u
#define OFF_OX 251904u
#define OFF_OY 946176u
#define OFF_OW 1640448u
#define OFF_OH 2334720u
#define OFF_OD 3028992u

// ---- static device scratch (no runtime allocation) ----
__device__ __align__(128) float g_k[BATCH * HDIM];
__device__ __align__(128) float g_v[BATCH * HDIM];
__device__ __align__(128) float g_kmin[BATCH];
__device__ __align__(128) float g_kmax[BATCH];
__device__ __align__(128) float g_Pclass[NCP * 1536];
__device__ __align__(128) float g_Wih_bins[6144 * 512];
__device__ __align__(128) float g_Pbin[(size_t)NBP * 6144];
__device__ __align__(128) float g_gi[(size_t)T_STEPS * BATCH * 1536];
__device__ __align__(128) float g_h[2 * BATCH * HDIM];
__device__ __align__(128) float g_Hall[(size_t)T_STEPS * BATCH * HDIM];
__device__ __align__(128) float g_Wcat[768 * 512];
__device__ __align__(128) float g_bcat[768];
__device__ __align__(128) float g_Chead[(size_t)3072 * 768];
__device__ unsigned g_bar;
__device__ unsigned g_snap;

__device__ __forceinline__ float ex2f(float x) {
    float y; asm("ex2.approx.ftz.f32 %0, %1;" : "=f"(y) : "f"(x)); return y;
}
__device__ __forceinline__ float sigmf(float x) {
    return 1.f / (1.f + ex2f(-x * LOG2E));
}
__device__ __forceinline__ float tanhf_f(float x) {
    x = fminf(fmaxf(x, -15.f), 15.f);
    float e = ex2f(-2.f * x * LOG2E);
    return (1.f - e) / (1.f + e);
}
__device__ __forceinline__ float4 add4(float4 a, const float* p) {
    float4 b = *(const float4*)p;
    a.x += b.x; a.y += b.y; a.z += b.z; a.w += b.w; return a;
}

// ---- img = x@Wb.T+bb -> k,v (one warp per output) ----
__global__ __launch_bounds__(256) void img_k(
    const float* __restrict__ xf, const float* __restrict__ Wb,
    const float* __restrict__ bb, const float* __restrict__ aiw,
    const float* __restrict__ aib)
{
    int gw = blockIdx.x * 8 + (threadIdx.x >> 5);
    int lane = threadIdx.x & 31;
    int b = gw >> 9, i = gw & 511;
    const float4* xr = (const float4*)(xf + (size_t)b * FEAT);
    const float4* wr = (const float4*)(Wb + (size_t)i * FEAT);
    float acc = 0.f;
#pragma unroll 4
    for (int m = 0; m < 16; ++m) {
        float4 a = xr[m * 32 + lane];
        float4 w = wr[m * 32 + lane];
        acc = fmaf(a.x, w.x, acc); acc = fmaf(a.y, w.y, acc);
        acc = fmaf(a.z, w.z, acc); acc = fmaf(a.w, w.w, acc);
    }
    for (int d = 16; d; d >>= 1) acc += __shfl_down_sync(0xffffffffu, acc, d);
    if (lane == 0) {
        acc += bb[i];
        g_k[b * 512 + i] = fmaf(acc, aiw[1], aib[1]);
        g_v[b * 512 + i] = fmaf(acc, aiw[2], aib[2]);
    }
}

// ---- pack W_ih bin blocks into contiguous [4*1536, 512] ----
__global__ __launch_bounds__(128) void pack_wih_k(const float* __restrict__ W_ih)
{
    int r = blockIdx.x;            // s*1536 + g
    int s = r / 1536;
    int g = r - s * 1536;
    int f = threadIdx.x << 2;
    float4 v = *(const float4*)(W_ih + (size_t)g * 2560 + 512 * (s + 1) + f);
    *(float4*)(g_Wih_bins + (size_t)r * 512 + f) = v;
}

// ---- per-batch k extrema + h0=0 + barrier snapshot ----
__global__ __launch_bounds__(512) void prep2_k()
{
    int blk = blockIdx.x, tid = threadIdx.x;
    if (blk < 32) {
        float v = g_k[blk * 512 + tid];
        float mn = v, mx = v;
        for (int d = 16; d; d >>= 1) {
            mn = fminf(mn, __shfl_down_sync(0xffffffffu, mn, d));
            mx = fmaxf(mx, __shfl_down_sync(0xffffffffu, mx, d));
        }
        __shared__ float smn[16], smx[16];
        if ((tid & 31) == 0) { smn[tid >> 5] = mn; smx[tid >> 5] = mx; }
        __syncthreads();
        if (tid == 0) {
            for (int w = 1; w < 16; ++w) { mn = fminf(mn, smn[w]); mx = fmaxf(mx, smx[w]); }
            g_kmin[blk] = mn; g_kmax[blk] = mx;
        }
    } else {
        for (int idx = tid; idx < BATCH * HDIM; idx += 512) g_h[idx] = 0.f;
        if (tid == 0) g_snap = g_bar;
    }
}

// ---- generic SGEMM: C[M,N] = A[M,K]@B[N,K]^T (+bias), BM128/BN64/BK16 ----
__global__ __launch_bounds__(256) void sgemm_nt(
    const float* __restrict__ A, int lda,
    const float* __restrict__ B, int ldb,
    const float* __restrict__ bias,
    float* __restrict__ C, int ldc, int M, int N, int K)
{
    __shared__ float As[16 * 132];
    __shared__ float Bs[16 * 68];
    int tid = threadIdx.x;
    int bm = blockIdx.y * 128, bn = blockIdx.x * 64;
    int tx = tid & 15, ty = tid >> 4;
    float acc[8][4];
#pragma unroll
    for (int i = 0; i < 8; ++i)
#pragma unroll
        for (int j = 0; j < 4; ++j) acc[i][j] = 0.f;
    int lr = tid >> 2, lk = (tid & 3) << 2;

    for (int kt = 0; kt < K; kt += 16) {
        float4 a0 = make_float4(0.f, 0.f, 0.f, 0.f), a1 = a0;
        int r0 = bm + lr, r1 = r0 + 64;
        if (r0 < M) a0 = *(const float4*)(A + (size_t)r0 * lda + kt + lk);
        if (r1 < M) a1 = *(const float4*)(A + (size_t)r1 * lda + kt + lk);
        float4 b0 = *(const float4*)(B + (size_t)(bn + lr) * ldb + kt + lk);
        __syncthreads();
        As[(lk + 0) * 132 + lr] = a0.x; As[(lk + 1) * 132 + lr] = a0.y;
        As[(lk + 2) * 132 + lr] = a0.z; As[(lk + 3) * 132 + lr] = a0.w;
        As[(lk + 0) * 132 + lr + 64] = a1.x; As[(lk + 1) * 132 + lr + 64] = a1.y;
        As[(lk + 2) * 132 + lr + 64] = a1.z; As[(lk + 3) * 132 + lr + 64] = a1.w;
        Bs[(lk + 0) * 68 + lr] = b0.x; Bs[(lk + 1) * 68 + lr] = b0.y;
        Bs[(lk + 2) * 68 + lr] = b0.z; Bs[(lk + 3) * 68 + lr] = b0.w;
        __syncthreads();
#pragma unroll
        for (int kk = 0; kk < 16; ++kk) {
            float ar[8], br[4];
            *(float4*)(ar)     = *(const float4*)&As[kk * 132 + ty * 8];
            *(float4*)(ar + 4) = *(const float4*)&As[kk * 132 + ty * 8 + 4];
            *(float4*)(br)     = *(const float4*)&Bs[kk * 68 + tx * 4];
#pragma unroll
            for (int i = 0; i < 8; ++i)
#pragma unroll
                for (int j = 0; j < 4; ++j)
                    acc[i][j] = fmaf(ar[i], br[j], acc[i][j]);
        }
    }
#pragma unroll
    for (int i = 0; i < 8; ++i) {
        int r = bm + ty * 8 + i;
        if (r < M) {
#pragma unroll
            for (int j = 0; j < 4; ++j) {
                int n = bn + tx * 4 + j;
                float v = acc[i][j];
                if (bias) v += bias[n];
                C[(size_t)r * ldc + n] = v;
            }
        }
    }
}

// ---- gi[t,b] = b_ih + Pclass[c] + sum Pbin_s[idx] ----
__global__ __launch_bounds__(384) void gather_k(
    const float* __restrict__ b_ih, const int* __restrict__ yc,
    const int* __restrict__ yx, const int* __restrict__ yy,
    const int* __restrict__ yw, const int* __restrict__ yh)
{
    int row = blockIdx.x;
    int t = row >> 5, b = row & 31;
    int c = 0, xi = 0, yi = 0, wi = 0, hi = 0;
    if (t > 0) {
        int o = b * T_STEPS + t - 1;
        c = yc[o]; xi = yx[o]; yi = yy[o]; wi = yw[o]; hi = yh[o];
    }
    int f = threadIdx.x << 2;
    float4 v = *(const float4*)(b_ih + f);
    v = add4(v, g_Pclass + (size_t)c * 1536 + f);
    v = add4(v, g_Pbin + (size_t)xi * 6144 + 0    + f);
    v = add4(v, g_Pbin + (size_t)yi * 6144 + 1536 + f);
    v = add4(v, g_Pbin + (size_t)wi * 6144 + 3072 + f);
    v = add4(v, g_Pbin + (size_t)hi * 6144 + 4608 + f);
    *(float4*)(g_gi + (size_t)row * 1536 + f) = v;
}

// ---- pack head weights: Wc | Wp[0:452) | Wp[678:904) | Wd | zeros ----
__global__ __launch_bounds__(128) void pack_k(
    const float* __restrict__ Wc, const float* __restrict__ bc,
    const float* __restrict__ Wp, const float* __restrict__ bp,
    const float* __restrict__ Wd, const float* __restrict__ bd)
{
    int r = blockIdx.x;
    const float* src = nullptr; float bv = 0.f;
    if (r < 82)       { src = Wc + (size_t)r * 512;         bv = bc[r]; }
    else if (r < 534) { src = Wp + (size_t)(r - 82) * 512;  bv = bp[r - 82]; }
    else if (r < 760) { src = Wp + (size_t)(r + 144) * 512; bv = bp[r + 144]; }
    else if (r < 763) { src = Wd + (size_t)(r - 760) * 512; bv = bd[r - 760]; }
    int f = threadIdx.x << 2;
    float4 v = src ? *(const float4*)(src + f) : make_float4(0.f, 0.f, 0.f, 0.f);
    *(float4*)(g_Wcat + (size_t)r * 512 + f) = v;
    if (threadIdx.x == 0) g_bcat[r] = bv;
}

// ---- persistent scan kernel ----
#define SM_K   0
#define SM_V   16384
#define SM_H   32768      /* stride 36 per hidden index */
#define SM_W   51200      /* 12 rows x 512 */
#define SM_Q   57344
#define SM_KMN 57472
#define SM_KMX 57504
#define SM_BH  57536
#define SM_TOT 57548      /* floats -> 230192 bytes */

__global__ void __launch_bounds__(512, 1) scan_k(
    const float* __restrict__ W_hh, const float* __restrict__ b_hh,
    const float* __restrict__ aiw, const float* __restrict__ aib,
    const float* __restrict__ aow, const float* __restrict__ aob)
{
    extern __shared__ float sm[];
    const int tid = threadIdx.x;
    const int i0 = blockIdx.x * 4;
    const float aw0 = aiw[0], ab0 = aib[0];
    const float ow = aow[0], ob = aob[0];
    const unsigned snap = *(volatile unsigned*)&g_snap;

    for (int idx = tid; idx < 16384; idx += 512) {
        sm[SM_K + idx] = g_k[idx];
        sm[SM_V + idx] = g_v[idx];
    }
    for (int idx = tid; idx < 6144; idx += 512) {
        int lr = idx >> 9, k = idx & 511;   // lr = gate*4 + ii
        sm[SM_W + idx] = W_hh[(size_t)((lr >> 2) * 512 + i0 + (lr & 3)) * 512 + k];
    }
    if (tid < 12) sm[SM_BH + tid] = b_hh[(tid >> 2) * 512 + i0 + (tid & 3)];
    if (tid < 32) { sm[SM_KMN + tid] = g_kmin[tid]; sm[SM_KMX + tid] = g_kmax[tid]; }
    __syncthreads();

    // phase A ids (tid < 256): 8-way contiguous k-split
    const int ii_a = tid >> 6;          // 0..3
    const int bg   = (tid >> 3) & 7;    // 0..7
    const int ks   = tid & 7;           // 0..7
    // attention ids (all 512)
    const int b_b = tid >> 4, ii_b = (tid >> 2) & 3, js = tid & 3;

    for (int t = 0; t < T_STEPS; ++t) {
        // load h_prev (written by other SMs) -> smem, stride-36 layout
        const float4* hsrc = (const float4*)(g_h + (t & 1) * 16384);
#pragma unroll
        for (int r = 0; r < 8; ++r) {
            int i4 = r * 512 + tid;
            float4 hv = __ldcg(hsrc + i4);
            int k = i4 >> 3, b0 = (i4 & 7) << 2;
            *(float4*)&sm[SM_H + k * 36 + b0] = hv;
        }
        __syncthreads();

        // phase A: gh = W_hh_slice @ h (256 threads, 8 warps), GRU, q
        if (tid < 256) {
            const int bsel = (bg << 2) | (ks & 3);
            float gir = 0.f, giz = 0.f, gin = 0.f;
            if (ks < 4) {
                const float* gp = g_gi + ((size_t)((t << 5) | bsel)) * 1536 + i0 + ii_a;
                gir = __ldg(gp); giz = __ldg(gp + 512); gin = __ldg(gp + 1024);
            }
            float a0[4] = {0.f,0.f,0.f,0.f}, a1[4] = {0.f,0.f,0.f,0.f}, a2[4] = {0.f,0.f,0.f,0.f};
            const float* wp = &sm[SM_W + ii_a * 512];
            const int kbase = ks << 6;           // contiguous 64-k chunk
#pragma unroll 4
            for (int m = 0; m < 64; ++m) {
                int k = kbase + m;
                float4 hv = *(const float4*)&sm[SM_H + k * 36 + (bg << 2)];
                float w0 = wp[k], w1 = wp[2048 + k], w2 = wp[4096 + k];
                a0[0] = fmaf(w0, hv.x, a0[0]); a0[1] = fmaf(w0, hv.y, a0[1]);
                a0[2] = fmaf(w0, hv.z, a0[2]); a0[3] = fmaf(w0, hv.w, a0[3]);
                a1[0] = fmaf(w1, hv.x, a1[0]); a1[1] = fmaf(w1, hv.y, a1[1]);
                a1[2] = fmaf(w1, hv.z, a1[2]); a1[3] = fmaf(w1, hv.w, a1[3]);
                a2[0] = fmaf(w2, hv.x, a2[0]); a2[1] = fmaf(w2, hv.y, a2[1]);
                a2[2] = fmaf(w2, hv.z, a2[2]); a2[3] = fmaf(w2, hv.w, a2[3]);
            }
#pragma unroll
            for (int j = 0; j < 4; ++j) {
                a0[j] += __shfl_xor_sync(0xffffffffu, a0[j], 1, 8);
                a0[j] += __shfl_xor_sync(0xffffffffu, a0[j], 2, 8);
                a0[j] += __shfl_xor_sync(0xffffffffu, a0[j], 4, 8);
                a1[j] += __shfl_xor_sync(0xffffffffu, a1[j], 1, 8);
                a1[j] += __shfl_xor_sync(0xffffffffu, a1[j], 2, 8);
                a1[j] += __shfl_xor_sync(0xffffffffu, a1[j], 4, 8);
                a2[j] += __shfl_xor_sync(0xffffffffu, a2[j], 1, 8);
                a2[j] += __shfl_xor_sync(0xffffffffu, a2[j], 2, 8);
                a2[j] += __shfl_xor_sync(0xffffffffu, a2[j], 4, 8);
            }
            if (ks < 4) {
                float ghr = a0[ks] + sm[SM_BH + ii_a];
                float ghz = a1[ks] + sm[SM_BH + 4 + ii_a];
                float ghn = a2[ks] + sm[SM_BH + 8 + ii_a];
                float r_ = sigmf(gir + ghr);
                float z_ = sigmf(giz + ghz);
                float n_ = tanhf_f(fmaf(r_, ghn, gin));
                float hp = sm[SM_H + (i0 + ii_a) * 36 + bsel];
                float hg = fmaf(1.f - z_, n_, z_ * hp);
                sm[SM_Q + (ii_a << 5) + bsel] = fmaf(hg, aw0, ab0);
            }
        }
        __syncthreads();

        // attention: rank-1 softmax over j (512), 4-way j-split per (b,i)
        {
            float q = sm[SM_Q + (ii_b << 5) + b_b];
            float mx = (q >= 0.f) ? q * sm[SM_KMX + b_b] : q * sm[SM_KMN + b_b];
            float ql = q * LOG2E, ml = mx * LOG2E;
            const float* kp = &sm[SM_K + (b_b << 9) + (js << 2)];
            const float* vp = &sm[SM_V + (b_b << 9) + (js << 2)];
            float se = 0.f, sv = 0.f;
#pragma unroll 4
            for (int m = 0; m < 32; ++m) {
                float4 kf = *(const float4*)(kp + (m << 4));
                float4 vf = *(const float4*)(vp + (m << 4));
                float e0 = ex2f(fmaf(ql, kf.x, -ml));
                float e1 = ex2f(fmaf(ql, kf.y, -ml));
                float e2 = ex2f(fmaf(ql, kf.z, -ml));
                float e3 = ex2f(fmaf(ql, kf.w, -ml));
                se += e0 + e1 + e2 + e3;
                sv = fmaf(e0, vf.x, sv); sv = fmaf(e1, vf.y, sv);
                sv = fmaf(e2, vf.z, sv); sv = fmaf(e3, vf.w, sv);
            }
            se += __shfl_xor_sync(0xffffffffu, se, 1, 4);
            se += __shfl_xor_sync(0xffffffffu, se, 2, 4);
            sv += __shfl_xor_sync(0xffffffffu, sv, 1, 4);
            sv += __shfl_xor_sync(0xffffffffu, sv, 2, 4);
            if (js == 0) {
                float hatt = fmaf(__fdividef(sv, se), ow, ob);
                int i = i0 + ii_b;
                g_Hall[(size_t)((t << 5) | b_b) * 512 + i] = hatt;
                if (t != T_STEPS - 1)
                    __stcg(&g_h[((t + 1) & 1) * 16384 + (i << 5) + b_b], hatt);
            }
        }

        if (t != T_STEPS - 1) {
            __syncthreads();
            if (tid == 0) {
                __threadfence();
                atomicAdd(&g_bar, 1u);
                unsigned target = snap + (unsigned)(t + 1) * NBLK;
                while ((int)(*(volatile unsigned*)&g_bar - target) < 0) { }
            }
            __syncthreads();
        }
    }
}

// ---- scatter heads to output (T,B)->(B,T), zero oh ----
__global__ __launch_bounds__(256) void scatter_k(float* __restrict__ out)
{
    int row = blockIdx.x;              // t*32 + b
    int t = row >> 5, b = row & 31;
    const float* src = g_Chead + (size_t)row * 768;
    int bt = b * 96 + t;
    for (int n = threadIdx.x; n < 226; n += 256) {
        if (n < 82) out[OFF_OC + (size_t)bt * 82 + n] = src[n];
        out[OFF_OX + (size_t)bt * 226 + n] = src[82 + n];
        out[OFF_OY + (size_t)bt * 226 + n] = src[308 + n];
        out[OFF_OW + (size_t)bt * 226 + n] = src[534 + n];
        out[OFF_OH + (size_t)bt * 226 + n] = 0.f;
        if (n < 3) out[OFF_OD + (size_t)bt * 3 + n] = src[760 + n];
    }
}

extern "C" void kernel_launch(void* const* d_in, const int* in_sizes, int n_in,
                              void* d_out, int out_size)
{
    const float* image_feat = (const float*)d_in[0];
    const int*   y_class    = (const int*)d_in[1];
    const int*   y_x        = (const int*)d_in[2];
    const int*   y_y        = (const int*)d_in[3];
    const int*   y_w        = (const int*)d_in[4];
    const int*   y_h        = (const int*)d_in[5];
    const float* class_emb  = (const float*)d_in[7];
    const float* bin_emb    = (const float*)d_in[8];
    const float* Wb         = (const float*)d_in[9];
    const float* bb         = (const float*)d_in[10];
    const float* W_ih       = (const float*)d_in[11];
    const float* b_ih       = (const float*)d_in[12];
    const float* W_hh       = (const float*)d_in[13];
    const float* b_hh       = (const float*)d_in[14];
    const float* aiw        = (const float*)d_in[15];
    const float* aib        = (const float*)d_in[16];
    const float* aow        = (const float*)d_in[17];
    const float* aob        = (const float*)d_in[18];
    const float* Wc         = (const float*)d_in[19];
    const float* bc         = (const float*)d_in[20];
    const float* Wp         = (const float*)d_in[21];
    const float* bp         = (const float*)d_in[22];
    const float* Wd         = (const float*)d_in[23];
    const float* bd         = (const float*)d_in[24];
    float* out = (float*)d_out;

    img_k<<<2048, 256>>>(image_feat, Wb, bb, aiw, aib);
    pack_wih_k<<<6144, 128>>>(W_ih);

    float* Pclass; cudaGetSymbolAddress((void**)&Pclass, g_Pclass);
    float* Pbin;   cudaGetSymbolAddress((void**)&Pbin, g_Pbin);
    float* Wihb;   cudaGetSymbolAddress((void**)&Wihb, g_Wih_bins);
    float* Hall;   cudaGetSymbolAddress((void**)&Hall, g_Hall);
    float* Wcat;   cudaGetSymbolAddress((void**)&Wcat, g_Wcat);
    float* bcat;   cudaGetSymbolAddress((void**)&bcat, g_bcat);
    float* Chead;  cudaGetSymbolAddress((void**)&Chead, g_Chead);

    // class table: Pclass = class_emb @ W_ih_block0^T
    sgemm_nt<<<dim3(24, 1), 256>>>(class_emb, 512, W_ih + 0, 2560, nullptr,
                                   Pclass, 1536, NCP, 1536, 512);
    // all 4 bin tables in ONE GEMM against packed W_ih bins
    sgemm_nt<<<dim3(96, 2), 256>>>(bin_emb, 512, Wihb, 512, nullptr,
                                   Pbin, 6144, NBP, 6144, 512);

    gather_k<<<T_STEPS * BATCH, 384>>>(b_ih, y_class, y_x, y_y, y_w, y_h);
    prep2_k<<<33, 512>>>();
    pack_k<<<768, 128>>>(Wc, bc, Wp, bp, Wd, bd);

    cudaFuncSetAttribute(scan_k, cudaFuncAttributeMaxDynamicSharedMemorySize,
                         SM_TOT * sizeof(float));
    scan_k<<<NBLK, 512, SM_TOT * sizeof(float)>>>(W_hh, b_hh, aiw, aib, aow, aob);

    // heads: Chead = Hall(3072x512) @ Wcat(768x512)^T + bcat
    sgemm_nt<<<dim3(12, 24), 256>>>(Hall, 512, Wcat, 512, bcat, Chead, 768, 3072, 768, 512);

    scatter_k<<<T_STEPS * BATCH, 256>>>(out);
}

// round 14
// speedup vs baseline: 2.2946x; 2.2946x over previous
#include <cuda_runtime.h>
#include <cstdint>

#define T_STEPS 96
#define BATCH   32
#define HDIM    512
#define NCP     82
#define NBP     226
#define FEAT    2048
#define NBLK    128
#define LOG2E   1.4426950408889634f

#define OFF_OC 0u
#define OFF_OX 251904u
#define OFF_OY 946176u
#define OFF_OW 1640448u
#define OFF_OH 2334720u
#define OFF_OD 3028992u

// ---- static device scratch (no runtime allocation) ----
__device__ __align__(128) float g_k[BATCH * HDIM];
__device__ __align__(128) float g_v[BATCH * HDIM];
__device__ __align__(128) float g_kmin[BATCH];
__device__ __align__(128) float g_kmax[BATCH];
__device__ __align__(128) float g_Pclass[NCP * 1536];
__device__ __align__(128) float g_Wih_bins[6144 * 512];
__device__ __align__(128) float g_Pbin[(size_t)NBP * 6144];
__device__ __align__(128) float g_gi[(size_t)T_STEPS * BATCH * 1536];
__device__ __align__(128) float g_h[2 * BATCH * HDIM];
__device__ __align__(128) float g_Hall[(size_t)T_STEPS * BATCH * HDIM];
__device__ __align__(128) float g_Wcat[768 * 512];
__device__ __align__(128) float g_bcat[768];
__device__ __align__(128) float g_Chead[(size_t)3072 * 768];
__device__ unsigned g_bar;
__device__ unsigned g_snap;

__device__ __forceinline__ float ex2f(float x) {
    float y; asm("ex2.approx.ftz.f32 %0, %1;" : "=f"(y) : "f"(x)); return y;
}
__device__ __forceinline__ float sigmf(float x) {
    return 1.f / (1.f + ex2f(-x * LOG2E));
}
__device__ __forceinline__ float tanhf_f(float x) {
    x = fminf(fmaxf(x, -15.f), 15.f);
    float e = ex2f(-2.f * x * LOG2E);
    return (1.f - e) / (1.f + e);
}
__device__ __forceinline__ float4 add4(float4 a, const float* p) {
    float4 b = *(const float4*)p;
    a.x += b.x; a.y += b.y; a.z += b.z; a.w += b.w; return a;
}

// ---- img = x@Wb.T+bb -> k,v (one warp per output) ----
__global__ __launch_bounds__(256) void img_k(
    const float* __restrict__ xf, const float* __restrict__ Wb,
    const float* __restrict__ bb, const float* __restrict__ aiw,
    const float* __restrict__ aib)
{
    int gw = blockIdx.x * 8 + (threadIdx.x >> 5);
    int lane = threadIdx.x & 31;
    int b = gw >> 9, i = gw & 511;
    const float4* xr = (const float4*)(xf + (size_t)b * FEAT);
    const float4* wr = (const float4*)(Wb + (size_t)i * FEAT);
    float acc = 0.f;
#pragma unroll 4
    for (int m = 0; m < 16; ++m) {
        float4 a = xr[m * 32 + lane];
        float4 w = wr[m * 32 + lane];
        acc = fmaf(a.x, w.x, acc); acc = fmaf(a.y, w.y, acc);
        acc = fmaf(a.z, w.z, acc); acc = fmaf(a.w, w.w, acc);
    }
    for (int d = 16; d; d >>= 1) acc += __shfl_down_sync(0xffffffffu, acc, d);
    if (lane == 0) {
        acc += bb[i];
        g_k[b * 512 + i] = fmaf(acc, aiw[1], aib[1]);
        g_v[b * 512 + i] = fmaf(acc, aiw[2], aib[2]);
    }
}

// ---- pack W_ih bin blocks into contiguous [4*1536, 512] ----
__global__ __launch_bounds__(128) void pack_wih_k(const float* __restrict__ W_ih)
{
    int r = blockIdx.x;            // s*1536 + g
    int s = r / 1536;
    int g = r - s * 1536;
    int f = threadIdx.x << 2;
    float4 v = *(const float4*)(W_ih + (size_t)g * 2560 + 512 * (s + 1) + f);
    *(float4*)(g_Wih_bins + (size_t)r * 512 + f) = v;
}

// ---- per-batch k extrema + h0=0 + barrier snapshot ----
__global__ __launch_bounds__(512) void prep2_k()
{
    int blk = blockIdx.x, tid = threadIdx.x;
    if (blk < 32) {
        float v = g_k[blk * 512 + tid];
        float mn = v, mx = v;
        for (int d = 16; d; d >>= 1) {
            mn = fminf(mn, __shfl_down_sync(0xffffffffu, mn, d));
            mx = fmaxf(mx, __shfl_down_sync(0xffffffffu, mx, d));
        }
        __shared__ float smn[16], smx[16];
        if ((tid & 31) == 0) { smn[tid >> 5] = mn; smx[tid >> 5] = mx; }
        __syncthreads();
        if (tid == 0) {
            for (int w = 1; w < 16; ++w) { mn = fminf(mn, smn[w]); mx = fmaxf(mx, smx[w]); }
            g_kmin[blk] = mn; g_kmax[blk] = mx;
        }
    } else {
        for (int idx = tid; idx < BATCH * HDIM; idx += 512) g_h[idx] = 0.f;
        if (tid == 0) g_snap = g_bar;
    }
}

// ---- generic SGEMM: C[M,N] = A[M,K]@B[N,K]^T (+bias), BM128/BN64/BK16 ----
__global__ __launch_bounds__(256) void sgemm_nt(
    const float* __restrict__ A, int lda,
    const float* __restrict__ B, int ldb,
    const float* __restrict__ bias,
    float* __restrict__ C, int ldc, int M, int N, int K)
{
    __shared__ float As[16 * 132];
    __shared__ float Bs[16 * 68];
    int tid = threadIdx.x;
    int bm = blockIdx.y * 128, bn = blockIdx.x * 64;
    int tx = tid & 15, ty = tid >> 4;
    float acc[8][4];
#pragma unroll
    for (int i = 0; i < 8; ++i)
#pragma unroll
        for (int j = 0; j < 4; ++j) acc[i][j] = 0.f;
    int lr = tid >> 2, lk = (tid & 3) << 2;

    for (int kt = 0; kt < K; kt += 16) {
        float4 a0 = make_float4(0.f, 0.f, 0.f, 0.f), a1 = a0;
        int r0 = bm + lr, r1 = r0 + 64;
        if (r0 < M) a0 = *(const float4*)(A + (size_t)r0 * lda + kt + lk);
        if (r1 < M) a1 = *(const float4*)(A + (size_t)r1 * lda + kt + lk);
        float4 b0 = *(const float4*)(B + (size_t)(bn + lr) * ldb + kt + lk);
        __syncthreads();
        As[(lk + 0) * 132 + lr] = a0.x; As[(lk + 1) * 132 + lr] = a0.y;
        As[(lk + 2) * 132 + lr] = a0.z; As[(lk + 3) * 132 + lr] = a0.w;
        As[(lk + 0) * 132 + lr + 64] = a1.x; As[(lk + 1) * 132 + lr + 64] = a1.y;
        As[(lk + 2) * 132 + lr + 64] = a1.z; As[(lk + 3) * 132 + lr + 64] = a1.w;
        Bs[(lk + 0) * 68 + lr] = b0.x; Bs[(lk + 1) * 68 + lr] = b0.y;
        Bs[(lk + 2) * 68 + lr] = b0.z; Bs[(lk + 3) * 68 + lr] = b0.w;
        __syncthreads();
#pragma unroll
        for (int kk = 0; kk < 16; ++kk) {
            float ar[8], br[4];
            *(float4*)(ar)     = *(const float4*)&As[kk * 132 + ty * 8];
            *(float4*)(ar + 4) = *(const float4*)&As[kk * 132 + ty * 8 + 4];
            *(float4*)(br)     = *(const float4*)&Bs[kk * 68 + tx * 4];
#pragma unroll
            for (int i = 0; i < 8; ++i)
#pragma unroll
                for (int j = 0; j < 4; ++j)
                    acc[i][j] = fmaf(ar[i], br[j], acc[i][j]);
        }
    }
#pragma unroll
    for (int i = 0; i < 8; ++i) {
        int r = bm + ty * 8 + i;
        if (r < M) {
#pragma unroll
            for (int j = 0; j < 4; ++j) {
                int n = bn + tx * 4 + j;
                float v = acc[i][j];
                if (bias) v += bias[n];
                C[(size_t)r * ldc + n] = v;
            }
        }
    }
}

// ---- gi[t,b] = b_ih + Pclass[c] + sum Pbin_s[idx] ----
__global__ __launch_bounds__(384) void gather_k(
    const float* __restrict__ b_ih, const int* __restrict__ yc,
    const int* __restrict__ yx, const int* __restrict__ yy,
    const int* __restrict__ yw, const int* __restrict__ yh)
{
    int row = blockIdx.x;
    int t = row >> 5, b = row & 31;
    int c = 0, xi = 0, yi = 0, wi = 0, hi = 0;
    if (t > 0) {
        int o = b * T_STEPS + t - 1;
        c = yc[o]; xi = yx[o]; yi = yy[o]; wi = yw[o]; hi = yh[o];
    }
    int f = threadIdx.x << 2;
    float4 v = *(const float4*)(b_ih + f);
    v = add4(v, g_Pclass + (size_t)c * 1536 + f);
    v = add4(v, g_Pbin + (size_t)xi * 6144 + 0    + f);
    v = add4(v, g_Pbin + (size_t)yi * 6144 + 1536 + f);
    v = add4(v, g_Pbin + (size_t)wi * 6144 + 3072 + f);
    v = add4(v, g_Pbin + (size_t)hi * 6144 + 4608 + f);
    *(float4*)(g_gi + (size_t)row * 1536 + f) = v;
}

// ---- pack head weights: Wc | Wp[0:452) | Wp[678:904) | Wd | zeros ----
__global__ __launch_bounds__(128) void pack_k(
    const float* __restrict__ Wc, const float* __restrict__ bc,
    const float* __restrict__ Wp, const float* __restrict__ bp,
    const float* __restrict__ Wd, const float* __restrict__ bd)
{
    int r = blockIdx.x;
    const float* src = nullptr; float bv = 0.f;
    if (r < 82)       { src = Wc + (size_t)r * 512;         bv = bc[r]; }
    else if (r < 534) { src = Wp + (size_t)(r - 82) * 512;  bv = bp[r - 82]; }
    else if (r < 760) { src = Wp + (size_t)(r + 144) * 512; bv = bp[r + 144]; }
    else if (r < 763) { src = Wd + (size_t)(r - 760) * 512; bv = bd[r - 760]; }
    int f = threadIdx.x << 2;
    float4 v = src ? *(const float4*)(src + f) : make_float4(0.f, 0.f, 0.f, 0.f);
    *(float4*)(g_Wcat + (size_t)r * 512 + f) = v;
    if (threadIdx.x == 0) g_bcat[r] = bv;
}

// ---- persistent scan kernel ----
#define SM_K   0
#define SM_V   16384
#define SM_H   32768      /* stride 36 per hidden index */
#define SM_W   51200      /* 12 rows x 512 */
#define SM_Q   57344
#define SM_KMN 57472
#define SM_KMX 57504
#define SM_BH  57536
#define SM_TOT 57548      /* floats -> 230192 bytes */

__global__ void __launch_bounds__(512, 1) scan_k(
    const float* __restrict__ W_hh, const float* __restrict__ b_hh,
    const float* __restrict__ aiw, const float* __restrict__ aib,
    const float* __restrict__ aow, const float* __restrict__ aob)
{
    extern __shared__ float sm[];
    const int tid = threadIdx.x;
    const int i0 = blockIdx.x * 4;
    const float aw0 = aiw[0], ab0 = aib[0];
    const float ow = aow[0], ob = aob[0];
    const unsigned snap = *(volatile unsigned*)&g_snap;

    for (int idx = tid; idx < 16384; idx += 512) {
        sm[SM_K + idx] = g_k[idx];
        sm[SM_V + idx] = g_v[idx];
    }
    for (int idx = tid; idx < 6144; idx += 512) {
        int lr = idx >> 9, k = idx & 511;   // lr = gate*4 + ii
        sm[SM_W + idx] = W_hh[(size_t)((lr >> 2) * 512 + i0 + (lr & 3)) * 512 + k];
    }
    if (tid < 12) sm[SM_BH + tid] = b_hh[(tid >> 2) * 512 + i0 + (tid & 3)];
    if (tid < 32) { sm[SM_KMN + tid] = g_kmin[tid]; sm[SM_KMX + tid] = g_kmax[tid]; }
    __syncthreads();

    // attention ids (all 512 threads)
    const int b_b = tid >> 4, ii_b = (tid >> 2) & 3, js = tid & 3;

    for (int t = 0; t < T_STEPS; ++t) {
        // load h_prev (written by other SMs) -> smem, stride-36 layout
        const float4* hsrc = (const float4*)(g_h + (t & 1) * 16384);
#pragma unroll
        for (int r = 0; r < 8; ++r) {
            int i4 = r * 512 + tid;
            float4 hv = __ldcg(hsrc + i4);
            int k = i4 >> 3, b0 = (i4 & 7) << 2;
            *(float4*)&sm[SM_H + k * 36 + b0] = hv;
        }
        __syncthreads();

        // phase A (threads 0..127): gh = W_hh_slice @ h, GRU, q
        // lane map: bg in LOW 3 bits so each 8-lane LDS phase has fixed k,
        // bg=0..7 -> start-bank-group (k+bg)%8 bijective -> conflict-free h,
        // and w loads are same-address broadcast within a phase.
        if (tid < 128) {
            const int ii_a = tid >> 5;       // 0..3 (warp id)
            const int ks   = (tid >> 3) & 3; // k-split
            const int bg   = tid & 7;        // batch quad
            const int bsel = (bg << 2) | ks; // this lane's batch after reduce

            const float* gp = g_gi + ((size_t)((t << 5) | bsel)) * 1536 + i0 + ii_a;
            float gir = __ldg(gp), giz = __ldg(gp + 512), gin = __ldg(gp + 1024);

            float a0[4] = {0.f,0.f,0.f,0.f}, a1[4] = {0.f,0.f,0.f,0.f}, a2[4] = {0.f,0.f,0.f,0.f};
            const float* wp = &sm[SM_W + ii_a * 512];
#pragma unroll 4
            for (int m = 0; m < 128; ++m) {
                int k = (m << 2) | ks;
                float4 hv = *(const float4*)&sm[SM_H + k * 36 + (bg << 2)];
                float w0 = wp[k], w1 = wp[2048 + k], w2 = wp[4096 + k];
                a0[0] = fmaf(w0, hv.x, a0[0]); a0[1] = fmaf(w0, hv.y, a0[1]);
                a0[2] = fmaf(w0, hv.z, a0[2]); a0[3] = fmaf(w0, hv.w, a0[3]);
                a1[0] = fmaf(w1, hv.x, a1[0]); a1[1] = fmaf(w1, hv.y, a1[1]);
                a1[2] = fmaf(w1, hv.z, a1[2]); a1[3] = fmaf(w1, hv.w, a1[3]);
                a2[0] = fmaf(w2, hv.x, a2[0]); a2[1] = fmaf(w2, hv.y, a2[1]);
                a2[2] = fmaf(w2, hv.z, a2[2]); a2[3] = fmaf(w2, hv.w, a2[3]);
            }
#pragma unroll
            for (int j = 0; j < 4; ++j) {
                a0[j] += __shfl_xor_sync(0xffffffffu, a0[j], 8);
                a0[j] += __shfl_xor_sync(0xffffffffu, a0[j], 16);
                a1[j] += __shfl_xor_sync(0xffffffffu, a1[j], 8);
                a1[j] += __shfl_xor_sync(0xffffffffu, a1[j], 16);
                a2[j] += __shfl_xor_sync(0xffffffffu, a2[j], 8);
                a2[j] += __shfl_xor_sync(0xffffffffu, a2[j], 16);
            }
            // lane ks of each k-split group takes batch bsel (column ks)
            float ghr = a0[ks] + sm[SM_BH + ii_a];
            float ghz = a1[ks] + sm[SM_BH + 4 + ii_a];
            float ghn = a2[ks] + sm[SM_BH + 8 + ii_a];
            float r_ = sigmf(gir + ghr);
            float z_ = sigmf(giz + ghz);
            float n_ = tanhf_f(fmaf(r_, ghn, gin));
            float hp = sm[SM_H + (i0 + ii_a) * 36 + bsel];
            float hg = fmaf(1.f - z_, n_, z_ * hp);
            sm[SM_Q + (ii_a << 5) + bsel] = fmaf(hg, aw0, ab0);
        }
        __syncthreads();

        // attention: rank-1 softmax over j (512), 4-way j-split per (b,i)
        {
            float q = sm[SM_Q + (ii_b << 5) + b_b];
            float mx = (q >= 0.f) ? q * sm[SM_KMX + b_b] : q * sm[SM_KMN + b_b];
            float ql = q * LOG2E, ml = mx * LOG2E;
            const float* kp = &sm[SM_K + (b_b << 9) + (js << 2)];
            const float* vp = &sm[SM_V + (b_b << 9) + (js << 2)];
            float se = 0.f, sv = 0.f;
#pragma unroll 4
            for (int m = 0; m < 32; ++m) {
                float4 kf = *(const float4*)(kp + (m << 4));
                float4 vf = *(const float4*)(vp + (m << 4));
                float e0 = ex2f(fmaf(ql, kf.x, -ml));
                float e1 = ex2f(fmaf(ql, kf.y, -ml));
                float e2 = ex2f(fmaf(ql, kf.z, -ml));
                float e3 = ex2f(fmaf(ql, kf.w, -ml));
                se += e0 + e1 + e2 + e3;
                sv = fmaf(e0, vf.x, sv); sv = fmaf(e1, vf.y, sv);
                sv = fmaf(e2, vf.z, sv); sv = fmaf(e3, vf.w, sv);
            }
            se += __shfl_xor_sync(0xffffffffu, se, 1, 4);
            se += __shfl_xor_sync(0xffffffffu, se, 2, 4);
            sv += __shfl_xor_sync(0xffffffffu, sv, 1, 4);
            sv += __shfl_xor_sync(0xffffffffu, sv, 2, 4);
            if (js == 0) {
                float hatt = fmaf(__fdividef(sv, se), ow, ob);
                int i = i0 + ii_b;
                g_Hall[(size_t)((t << 5) | b_b) * 512 + i] = hatt;
                if (t != T_STEPS - 1)
                    __stcg(&g_h[((t + 1) & 1) * 16384 + (i << 5) + b_b], hatt);
            }
        }

        if (t != T_STEPS - 1) {
            __syncthreads();
            if (tid == 0) {
                __threadfence();
                atomicAdd(&g_bar, 1u);
                unsigned target = snap + (unsigned)(t + 1) * NBLK;
                while ((int)(*(volatile unsigned*)&g_bar - target) < 0) { }
            }
            __syncthreads();
        }
    }
}

// ---- scatter heads to output (T,B)->(B,T), zero oh ----
__global__ __launch_bounds__(256) void scatter_k(float* __restrict__ out)
{
    int row = blockIdx.x;              // t*32 + b
    int t = row >> 5, b = row & 31;
    const float* src = g_Chead + (size_t)row * 768;
    int bt = b * 96 + t;
    for (int n = threadIdx.x; n < 226; n += 256) {
        if (n < 82) out[OFF_OC + (size_t)bt * 82 + n] = src[n];
        out[OFF_OX + (size_t)bt * 226 + n] = src[82 + n];
        out[OFF_OY + (size_t)bt * 226 + n] = src[308 + n];
        out[OFF_OW + (size_t)bt * 226 + n] = src[534 + n];
        out[OFF_OH + (size_t)bt * 226 + n] = 0.f;
        if (n < 3) out[OFF_OD + (size_t)bt * 3 + n] = src[760 + n];
    }
}

extern "C" void kernel_launch(void* const* d_in, const int* in_sizes, int n_in,
                              void* d_out, int out_size)
{
    const float* image_feat = (const float*)d_in[0];
    const int*   y_class    = (const int*)d_in[1];
    const int*   y_x        = (const int*)d_in[2];
    const int*   y_y        = (const int*)d_in[3];
    const int*   y_w        = (const int*)d_in[4];
    const int*   y_h        = (const int*)d_in[5];
    const float* class_emb  = (const float*)d_in[7];
    const float* bin_emb    = (const float*)d_in[8];
    const float* Wb         = (const float*)d_in[9];
    const float* bb         = (const float*)d_in[10];
    const float* W_ih       = (const float*)d_in[11];
    const float* b_ih       = (const float*)d_in[12];
    const float* W_hh       = (const float*)d_in[13];
    const float* b_hh       = (const float*)d_in[14];
    const float* aiw        = (const float*)d_in[15];
    const float* aib        = (const float*)d_in[16];
    const float* aow        = (const float*)d_in[17];
    const float* aob        = (const float*)d_in[18];
    const float* Wc         = (const float*)d_in[19];
    const float* bc         = (const float*)d_in[20];
    const float* Wp         = (const float*)d_in[21];
    const float* bp         = (const float*)d_in[22];
    const float* Wd         = (const float*)d_in[23];
    const float* bd         = (const float*)d_in[24];
    float* out = (float*)d_out;

    img_k<<<2048, 256>>>(image_feat, Wb, bb, aiw, aib);
    pack_wih_k<<<6144, 128>>>(W_ih);

    float* Pclass; cudaGetSymbolAddress((void**)&Pclass, g_Pclass);
    float* Pbin;   cudaGetSymbolAddress((void**)&Pbin, g_Pbin);
    float* Wihb;   cudaGetSymbolAddress((void**)&Wihb, g_Wih_bins);
    float* Hall;   cudaGetSymbolAddress((void**)&Hall, g_Hall);
    float* Wcat;   cudaGetSymbolAddress((void**)&Wcat, g_Wcat);
    float* bcat;   cudaGetSymbolAddress((void**)&bcat, g_bcat);
    float* Chead;  cudaGetSymbolAddress((void**)&Chead, g_Chead);

    // class table: Pclass = class_emb @ W_ih_block0^T
    sgemm_nt<<<dim3(24, 1), 256>>>(class_emb, 512, W_ih + 0, 2560, nullptr,
                                   Pclass, 1536, NCP, 1536, 512);
    // all 4 bin tables in ONE GEMM against packed W_ih bins
    sgemm_nt<<<dim3(96, 2), 256>>>(bin_emb, 512, Wihb, 512, nullptr,
                                   Pbin, 6144, NBP, 6144, 512);

    gather_k<<<T_STEPS * BATCH, 384>>>(b_ih, y_class, y_x, y_y, y_w, y_h);
    prep2_k<<<33, 512>>>();
    pack_k<<<768, 128>>>(Wc, bc, Wp, bp, Wd, bd);

    cudaFuncSetAttribute(scan_k, cudaFuncAttributeMaxDynamicSharedMemorySize,
                         SM_TOT * sizeof(float));
    scan_k<<<NBLK, 512, SM_TOT * sizeof(float)>>>(W_hh, b_hh, aiw, aib, aow, aob);

    // heads: Chead = Hall(3072x512) @ Wcat(768x512)^T + bcat
    sgemm_nt<<<dim3(12, 24), 256>>>(Hall, 512, Wcat, 512, bcat, Chead, 768, 3072, 768, 512);

    scatter_k<<<T_STEPS * BATCH, 256>>>(out);
}

// round 15
// speedup vs baseline: 2.6447x; 1.1526x over previous
#include <cuda_runtime.h>
#include <cstdint>

#define T_STEPS 96
#define BATCH   32
#define HDIM    512
#define NCP     82
#define NBP     226
#define FEAT    2048
#define NBLK    128
#define NTAB    2048
#define LOG2E   1.4426950408889634f

#define OFF_OC 0u
#define OFF_OX 251904u
#define OFF_OY 946176u
#define OFF_OW 1640448u
#define OFF_OH 2334720u
#define OFF_OD 3028992u

// ---- static device scratch (no runtime allocation) ----
__device__ __align__(128) float g_k[BATCH * HDIM];
__device__ __align__(128) float g_v[BATCH * HDIM];
__device__ __align__(128) float g_kmin[BATCH];
__device__ __align__(128) float g_kmax[BATCH];
__device__ __align__(128) float g_qlo[BATCH];
__device__ __align__(128) float g_qstep[BATCH];
__device__ __align__(128) float g_qinv[BATCH];
__device__ __align__(128) float g_tab[(size_t)BATCH * NTAB * 8];
__device__ __align__(128) float g_Pclass[NCP * 1536];
__device__ __align__(128) float g_Wih_bins[6144 * 512];
__device__ __align__(128) float g_Pbin[(size_t)NBP * 6144];
__device__ __align__(128) float g_gi[(size_t)T_STEPS * BATCH * 1536];
__device__ __align__(128) float g_h[2 * BATCH * HDIM];
__device__ __align__(128) float g_Hall[(size_t)T_STEPS * BATCH * HDIM];
__device__ __align__(128) float g_Wcat[768 * 512];
__device__ __align__(128) float g_bcat[768];
__device__ __align__(128) float g_Chead[(size_t)3072 * 768];
__device__ unsigned g_bar;
__device__ unsigned g_snap;

__device__ __forceinline__ float ex2f(float x) {
    float y; asm("ex2.approx.ftz.f32 %0, %1;" : "=f"(y) : "f"(x)); return y;
}
__device__ __forceinline__ float sigmf(float x) {
    return 1.f / (1.f + ex2f(-x * LOG2E));
}
__device__ __forceinline__ float tanhf_f(float x) {
    x = fminf(fmaxf(x, -15.f), 15.f);
    float e = ex2f(-2.f * x * LOG2E);
    return (1.f - e) / (1.f + e);
}
__device__ __forceinline__ float4 add4(float4 a, const float* p) {
    float4 b = *(const float4*)p;
    a.x += b.x; a.y += b.y; a.z += b.z; a.w += b.w; return a;
}

// ---- img = x@Wb.T+bb -> k,v (one warp per output) ----
__global__ __launch_bounds__(256) void img_k(
    const float* __restrict__ xf, const float* __restrict__ Wb,
    const float* __restrict__ bb, const float* __restrict__ aiw,
    const float* __restrict__ aib)
{
    int gw = blockIdx.x * 8 + (threadIdx.x >> 5);
    int lane = threadIdx.x & 31;
    int b = gw >> 9, i = gw & 511;
    const float4* xr = (const float4*)(xf + (size_t)b * FEAT);
    const float4* wr = (const float4*)(Wb + (size_t)i * FEAT);
    float acc = 0.f;
#pragma unroll 4
    for (int m = 0; m < 16; ++m) {
        float4 a = xr[m * 32 + lane];
        float4 w = wr[m * 32 + lane];
        acc = fmaf(a.x, w.x, acc); acc = fmaf(a.y, w.y, acc);
        acc = fmaf(a.z, w.z, acc); acc = fmaf(a.w, w.w, acc);
    }
    for (int d = 16; d; d >>= 1) acc += __shfl_down_sync(0xffffffffu, acc, d);
    if (lane == 0) {
        acc += bb[i];
        g_k[b * 512 + i] = fmaf(acc, aiw[1], aib[1]);
        g_v[b * 512 + i] = fmaf(acc, aiw[2], aib[2]);
    }
}

// ---- pack W_ih bin blocks into contiguous [4*1536, 512] ----
__global__ __launch_bounds__(128) void pack_wih_k(const float* __restrict__ W_ih)
{
    int r = blockIdx.x;
    int s = r / 1536;
    int g = r - s * 1536;
    int f = threadIdx.x << 2;
    float4 v = *(const float4*)(W_ih + (size_t)g * 2560 + 512 * (s + 1) + f);
    *(float4*)(g_Wih_bins + (size_t)r * 512 + f) = v;
}

// ---- per-batch k/v extrema, q-range, h0=0, barrier snapshot ----
__global__ __launch_bounds__(512) void prep2_k(
    const float* __restrict__ aiw, const float* __restrict__ aib,
    const float* __restrict__ aow, const float* __restrict__ aob)
{
    int blk = blockIdx.x, tid = threadIdx.x;
    if (blk < 32) {
        float kv = g_k[blk * 512 + tid], vv = g_v[blk * 512 + tid];
        float kmn = kv, kmx = kv, vmn = vv, vmx = vv;
        for (int d = 16; d; d >>= 1) {
            kmn = fminf(kmn, __shfl_xor_sync(0xffffffffu, kmn, d));
            kmx = fmaxf(kmx, __shfl_xor_sync(0xffffffffu, kmx, d));
            vmn = fminf(vmn, __shfl_xor_sync(0xffffffffu, vmn, d));
            vmx = fmaxf(vmx, __shfl_xor_sync(0xffffffffu, vmx, d));
        }
        __shared__ float s4[4][16];
        if ((tid & 31) == 0) {
            s4[0][tid >> 5] = kmn; s4[1][tid >> 5] = kmx;
            s4[2][tid >> 5] = vmn; s4[3][tid >> 5] = vmx;
        }
        __syncthreads();
        if (tid == 0) {
            for (int w = 1; w < 16; ++w) {
                kmn = fminf(kmn, s4[0][w]); kmx = fmaxf(kmx, s4[1][w]);
                vmn = fminf(vmn, s4[2][w]); vmx = fmaxf(vmx, s4[3][w]);
            }
            g_kmin[blk] = kmn; g_kmax[blk] = kmx;
            // rigorous q bound: ctx in [vmn,vmx]; h_att = ctx*ow+ob;
            // h_gru in hull{-1, 1, h_att range}; q = h_gru*aw + ab
            float ow = aow[0], ob = aob[0];
            float ca = fminf(ow * vmn, ow * vmx) + ob;
            float cb = fmaxf(ow * vmn, ow * vmx) + ob;
            float lo = fminf(-1.f, ca), hi = fmaxf(1.f, cb);
            float aw = aiw[0], ab = aib[0];
            float q1 = fmaf(aw, lo, ab), q2 = fmaf(aw, hi, ab);
            float qlo = fminf(q1, q2), qhi = fmaxf(q1, q2);
            float rng = fmaxf(qhi - qlo, 1e-3f);
            qlo -= 0.002f * rng; qhi += 0.002f * rng; rng = qhi - qlo;
            g_qlo[blk] = qlo;
            g_qstep[blk] = rng / (float)(NTAB - 1);
            g_qinv[blk] = (float)(NTAB - 1) / rng;
        }
    } else {
        for (int idx = tid; idx < BATCH * HDIM; idx += 512) g_h[idx] = 0.f;
        if (tid == 0) g_snap = g_bar;
    }
}

// ---- build per-batch rank-1 softmax moment table ----
// node q0: store S0..S3 (denominator moments, /m!) and W0..W3 (numerator),
// weights t_j = exp(q0*k_j - M) (scale cancels in the ratio).
__global__ __launch_bounds__(256) void tab_k()
{
    int warp = threadIdx.x >> 5, lane = threadIdx.x & 31;
    int idx = blockIdx.x * 8 + warp;
    int b = blockIdx.y;
    float qlo = g_qlo[b], step = g_qstep[b];
    float q0 = fmaf((float)idx, step, qlo);
    float M = (q0 >= 0.f) ? q0 * g_kmax[b] : q0 * g_kmin[b];
    float s0 = 0.f, s1 = 0.f, s2 = 0.f, s3 = 0.f;
    float w0 = 0.f, w1 = 0.f, w2 = 0.f, w3 = 0.f;
    const float* kp = g_k + b * 512;
    const float* vp = g_v + b * 512;
#pragma unroll 4
    for (int jj = 0; jj < 16; ++jj) {
        int j = jj * 32 + lane;
        float k = kp[j], v = vp[j];
        float t = ex2f(fmaf(q0, k, -M) * LOG2E);
        float tk = t * k, tk2 = tk * k, tk3 = tk2 * k;
        s0 += t; s1 += tk; s2 += tk2; s3 += tk3;
        w0 = fmaf(t, v, w0); w1 = fmaf(tk, v, w1);
        w2 = fmaf(tk2, v, w2); w3 = fmaf(tk3, v, w3);
    }
#pragma unroll
    for (int d = 16; d; d >>= 1) {
        s0 += __shfl_xor_sync(0xffffffffu, s0, d);
        s1 += __shfl_xor_sync(0xffffffffu, s1, d);
        s2 += __shfl_xor_sync(0xffffffffu, s2, d);
        s3 += __shfl_xor_sync(0xffffffffu, s3, d);
        w0 += __shfl_xor_sync(0xffffffffu, w0, d);
        w1 += __shfl_xor_sync(0xffffffffu, w1, d);
        w2 += __shfl_xor_sync(0xffffffffu, w2, d);
        w3 += __shfl_xor_sync(0xffffffffu, w3, d);
    }
    if (lane == 0) {
        float* o = g_tab + (((size_t)b * NTAB + idx) << 3);
        *(float4*)o       = make_float4(s0, s1, s2 * 0.5f, s3 * (1.f / 6.f));
        *(float4*)(o + 4) = make_float4(w0, w1, w2 * 0.5f, w3 * (1.f / 6.f));
    }
}

// ---- generic SGEMM: C[M,N] = A[M,K]@B[N,K]^T (+bias), BM128/BN64/BK16 ----
__global__ __launch_bounds__(256) void sgemm_nt(
    const float* __restrict__ A, int lda,
    const float* __restrict__ B, int ldb,
    const float* __restrict__ bias,
    float* __restrict__ C, int ldc, int M, int N, int K)
{
    __shared__ float As[16 * 132];
    __shared__ float Bs[16 * 68];
    int tid = threadIdx.x;
    int bm = blockIdx.y * 128, bn = blockIdx.x * 64;
    int tx = tid & 15, ty = tid >> 4;
    float acc[8][4];
#pragma unroll
    for (int i = 0; i < 8; ++i)
#pragma unroll
        for (int j = 0; j < 4; ++j) acc[i][j] = 0.f;
    int lr = tid >> 2, lk = (tid & 3) << 2;

    for (int kt = 0; kt < K; kt += 16) {
        float4 a0 = make_float4(0.f, 0.f, 0.f, 0.f), a1 = a0;
        int r0 = bm + lr, r1 = r0 + 64;
        if (r0 < M) a0 = *(const float4*)(A + (size_t)r0 * lda + kt + lk);
        if (r1 < M) a1 = *(const float4*)(A + (size_t)r1 * lda + kt + lk);
        float4 b0 = *(const float4*)(B + (size_t)(bn + lr) * ldb + kt + lk);
        __syncthreads();
        As[(lk + 0) * 132 + lr] = a0.x; As[(lk + 1) * 132 + lr] = a0.y;
        As[(lk + 2) * 132 + lr] = a0.z; As[(lk + 3) * 132 + lr] = a0.w;
        As[(lk + 0) * 132 + lr + 64] = a1.x; As[(lk + 1) * 132 + lr + 64] = a1.y;
        As[(lk + 2) * 132 + lr + 64] = a1.z; As[(lk + 3) * 132 + lr + 64] = a1.w;
        Bs[(lk + 0) * 68 + lr] = b0.x; Bs[(lk + 1) * 68 + lr] = b0.y;
        Bs[(lk + 2) * 68 + lr] = b0.z; Bs[(lk + 3) * 68 + lr] = b0.w;
        __syncthreads();
#pragma unroll
        for (int kk = 0; kk < 16; ++kk) {
            float ar[8], br[4];
            *(float4*)(ar)     = *(const float4*)&As[kk * 132 + ty * 8];
            *(float4*)(ar + 4) = *(const float4*)&As[kk * 132 + ty * 8 + 4];
            *(float4*)(br)     = *(const float4*)&Bs[kk * 68 + tx * 4];
#pragma unroll
            for (int i = 0; i < 8; ++i)
#pragma unroll
                for (int j = 0; j < 4; ++j)
                    acc[i][j] = fmaf(ar[i], br[j], acc[i][j]);
        }
    }
#pragma unroll
    for (int i = 0; i < 8; ++i) {
        int r = bm + ty * 8 + i;
        if (r < M) {
#pragma unroll
            for (int j = 0; j < 4; ++j) {
                int n = bn + tx * 4 + j;
                float v = acc[i][j];
                if (bias) v += bias[n];
                C[(size_t)r * ldc + n] = v;
            }
        }
    }
}

// ---- gi[t,b] = b_ih + Pclass[c] + sum Pbin_s[idx] ----
__global__ __launch_bounds__(384) void gather_k(
    const float* __restrict__ b_ih, const int* __restrict__ yc,
    const int* __restrict__ yx, const int* __restrict__ yy,
    const int* __restrict__ yw, const int* __restrict__ yh)
{
    int row = blockIdx.x;
    int t = row >> 5, b = row & 31;
    int c = 0, xi = 0, yi = 0, wi = 0, hi = 0;
    if (t > 0) {
        int o = b * T_STEPS + t - 1;
        c = yc[o]; xi = yx[o]; yi = yy[o]; wi = yw[o]; hi = yh[o];
    }
    int f = threadIdx.x << 2;
    float4 v = *(const float4*)(b_ih + f);
    v = add4(v, g_Pclass + (size_t)c * 1536 + f);
    v = add4(v, g_Pbin + (size_t)xi * 6144 + 0    + f);
    v = add4(v, g_Pbin + (size_t)yi * 6144 + 1536 + f);
    v = add4(v, g_Pbin + (size_t)wi * 6144 + 3072 + f);
    v = add4(v, g_Pbin + (size_t)hi * 6144 + 4608 + f);
    *(float4*)(g_gi + (size_t)row * 1536 + f) = v;
}

// ---- pack head weights: Wc | Wp[0:452) | Wp[678:904) | Wd | zeros ----
__global__ __launch_bounds__(128) void pack_k(
    const float* __restrict__ Wc, const float* __restrict__ bc,
    const float* __restrict__ Wp, const float* __restrict__ bp,
    const float* __restrict__ Wd, const float* __restrict__ bd)
{
    int r = blockIdx.x;
    const float* src = nullptr; float bv = 0.f;
    if (r < 82)       { src = Wc + (size_t)r * 512;         bv = bc[r]; }
    else if (r < 534) { src = Wp + (size_t)(r - 82) * 512;  bv = bp[r - 82]; }
    else if (r < 760) { src = Wp + (size_t)(r + 144) * 512; bv = bp[r + 144]; }
    else if (r < 763) { src = Wd + (size_t)(r - 760) * 512; bv = bd[r - 760]; }
    int f = threadIdx.x << 2;
    float4 v = src ? *(const float4*)(src + f) : make_float4(0.f, 0.f, 0.f, 0.f);
    *(float4*)(g_Wcat + (size_t)r * 512 + f) = v;
    if (threadIdx.x == 0) g_bcat[r] = bv;
}

// ---- persistent scan kernel: 128 blocks x 128 threads ----
#define SM_H   0          /* 512 * 36 = 18432 */
#define SM_W   18432      /* 12 rows x 512 = 6144 */
#define SM_BH  24576      /* 12 */
#define SM_QL  24588
#define SM_QS  24620
#define SM_QI  24652
#define SM_TOT 24684      /* floats -> 98736 bytes */

__global__ void __launch_bounds__(128, 1) scan_k(
    const float* __restrict__ W_hh, const float* __restrict__ b_hh,
    const float* __restrict__ aiw, const float* __restrict__ aib,
    const float* __restrict__ aow, const float* __restrict__ aob)
{
    extern __shared__ float sm[];
    const int tid = threadIdx.x;
    const int i0 = blockIdx.x * 4;
    const float aw0 = aiw[0], ab0 = aib[0];
    const float ow = aow[0], ob = aob[0];
    const unsigned snap = *(volatile unsigned*)&g_snap;

    for (int idx = tid; idx < 6144; idx += 128) {
        int lr = idx >> 9, k = idx & 511;   // lr = gate*4 + ii
        sm[SM_W + idx] = W_hh[(size_t)((lr >> 2) * 512 + i0 + (lr & 3)) * 512 + k];
    }
    if (tid < 12) sm[SM_BH + tid] = b_hh[(tid >> 2) * 512 + i0 + (tid & 3)];
    if (tid < 32) {
        sm[SM_QL + tid] = g_qlo[tid];
        sm[SM_QS + tid] = g_qstep[tid];
        sm[SM_QI + tid] = g_qinv[tid];
    }
    __syncthreads();

    // lane map: bg in LOW 3 bits -> conflict-free h LDS + broadcast w LDS
    const int ii = tid >> 5;          // 0..3 (warp id)
    const int ks = (tid >> 3) & 3;    // k-split
    const int bg = tid & 7;           // batch quad
    const int bsel = (bg << 2) | ks;  // this lane's batch after reduce

    for (int t = 0; t < T_STEPS; ++t) {
        // prefetch gi (independent of h; hides under h exchange)
        const float* gp = g_gi + ((size_t)((t << 5) | bsel)) * 1536 + i0 + ii;
        float gir = __ldg(gp), giz = __ldg(gp + 512), gin = __ldg(gp + 1024);

        // load h_prev (written by other SMs) -> smem, stride-36 layout
        const float4* hsrc = (const float4*)(g_h + (t & 1) * 16384);
#pragma unroll 8
        for (int r = 0; r < 32; ++r) {
            int i4 = r * 128 + tid;
            float4 hv = __ldcg(hsrc + i4);
            int k = i4 >> 3, b0 = (i4 & 7) << 2;
            *(float4*)&sm[SM_H + k * 36 + b0] = hv;
        }
        __syncthreads();

        // gh = W_hh_slice @ h (all 128 threads), GRU
        float a0[4] = {0.f,0.f,0.f,0.f}, a1[4] = {0.f,0.f,0.f,0.f}, a2[4] = {0.f,0.f,0.f,0.f};
        const float* wp = &sm[SM_W + ii * 512];
#pragma unroll 4
        for (int m = 0; m < 128; ++m) {
            int k = (m << 2) | ks;
            float4 hv = *(const float4*)&sm[SM_H + k * 36 + (bg << 2)];
            float w0 = wp[k], w1 = wp[2048 + k], w2 = wp[4096 + k];
            a0[0] = fmaf(w0, hv.x, a0[0]); a0[1] = fmaf(w0, hv.y, a0[1]);
            a0[2] = fmaf(w0, hv.z, a0[2]); a0[3] = fmaf(w0, hv.w, a0[3]);
            a1[0] = fmaf(w1, hv.x, a1[0]); a1[1] = fmaf(w1, hv.y, a1[1]);
            a1[2] = fmaf(w1, hv.z, a1[2]); a1[3] = fmaf(w1, hv.w, a1[3]);
            a2[0] = fmaf(w2, hv.x, a2[0]); a2[1] = fmaf(w2, hv.y, a2[1]);
            a2[2] = fmaf(w2, hv.z, a2[2]); a2[3] = fmaf(w2, hv.w, a2[3]);
        }
#pragma unroll
        for (int j = 0; j < 4; ++j) {
            a0[j] += __shfl_xor_sync(0xffffffffu, a0[j], 8);
            a0[j] += __shfl_xor_sync(0xffffffffu, a0[j], 16);
            a1[j] += __shfl_xor_sync(0xffffffffu, a1[j], 8);
            a1[j] += __shfl_xor_sync(0xffffffffu, a1[j], 16);
            a2[j] += __shfl_xor_sync(0xffffffffu, a2[j], 8);
            a2[j] += __shfl_xor_sync(0xffffffffu, a2[j], 16);
        }
        float ghr = a0[ks] + sm[SM_BH + ii];
        float ghz = a1[ks] + sm[SM_BH + 4 + ii];
        float ghn = a2[ks] + sm[SM_BH + 8 + ii];
        float r_ = sigmf(gir + ghr);
        float z_ = sigmf(giz + ghz);
        float n_ = tanhf_f(fmaf(r_, ghn, gin));
        float hp = sm[SM_H + (i0 + ii) * 36 + bsel];
        float hg = fmaf(1.f - z_, n_, z_ * hp);

        // rank-1 attention via cubic moment table: ctx = W(dq)/S(dq)
        float q = fmaf(hg, aw0, ab0);
        float qlo = sm[SM_QL + bsel];
        float u = (q - qlo) * sm[SM_QI + bsel];
        u = fminf(fmaxf(u, 0.f), (float)(NTAB - 1));
        int idx = (int)(u + 0.5f);
        float dq = q - fmaf((float)idx, sm[SM_QS + bsel], qlo);
        const float4* tp = (const float4*)(g_tab + (((size_t)bsel * NTAB + idx) << 3));
        float4 S = __ldg(tp);
        float4 Wm = __ldg(tp + 1);
        float den = fmaf(dq, fmaf(dq, fmaf(dq, S.w, S.z), S.y), S.x);
        float num = fmaf(dq, fmaf(dq, fmaf(dq, Wm.w, Wm.z), Wm.y), Wm.x);
        float hatt = fmaf(__fdividef(num, den), ow, ob);

        g_Hall[(size_t)((t << 5) | bsel) * 512 + i0 + ii] = hatt;
        if (t != T_STEPS - 1) {
            __stcg(&g_h[((t + 1) & 1) * 16384 + ((i0 + ii) << 5) + bsel], hatt);
            __syncthreads();
            if (tid == 0) {
                __threadfence();
                atomicAdd(&g_bar, 1u);
                unsigned target = snap + (unsigned)(t + 1) * NBLK;
                while ((int)(*(volatile unsigned*)&g_bar - target) < 0) { }
            }
            __syncthreads();
        }
    }
}

// ---- scatter heads to output (T,B)->(B,T), zero oh ----
__global__ __launch_bounds__(256) void scatter_k(float* __restrict__ out)
{
    int row = blockIdx.x;              // t*32 + b
    int t = row >> 5, b = row & 31;
    const float* src = g_Chead + (size_t)row * 768;
    int bt = b * 96 + t;
    for (int n = threadIdx.x; n < 226; n += 256) {
        if (n < 82) out[OFF_OC + (size_t)bt * 82 + n] = src[n];
        out[OFF_OX + (size_t)bt * 226 + n] = src[82 + n];
        out[OFF_OY + (size_t)bt * 226 + n] = src[308 + n];
        out[OFF_OW + (size_t)bt * 226 + n] = src[534 + n];
        out[OFF_OH + (size_t)bt * 226 + n] = 0.f;
        if (n < 3) out[OFF_OD + (size_t)bt * 3 + n] = src[760 + n];
    }
}

extern "C" void kernel_launch(void* const* d_in, const int* in_sizes, int n_in,
                              void* d_out, int out_size)
{
    const float* image_feat = (const float*)d_in[0];
    const int*   y_class    = (const int*)d_in[1];
    const int*   y_x        = (const int*)d_in[2];
    const int*   y_y        = (const int*)d_in[3];
    const int*   y_w        = (const int*)d_in[4];
    const int*   y_h        = (const int*)d_in[5];
    const float* class_emb  = (const float*)d_in[7];
    const float* bin_emb    = (const float*)d_in[8];
    const float* Wb         = (const float*)d_in[9];
    const float* bb         = (const float*)d_in[10];
    const float* W_ih       = (const float*)d_in[11];
    const float* b_ih       = (const float*)d_in[12];
    const float* W_hh       = (const float*)d_in[13];
    const float* b_hh       = (const float*)d_in[14];
    const float* aiw        = (const float*)d_in[15];
    const float* aib        = (const float*)d_in[16];
    const float* aow        = (const float*)d_in[17];
    const float* aob        = (const float*)d_in[18];
    const float* Wc         = (const float*)d_in[19];
    const float* bc         = (const float*)d_in[20];
    const float* Wp         = (const float*)d_in[21];
    const float* bp         = (const float*)d_in[22];
    const float* Wd         = (const float*)d_in[23];
    const float* bd         = (const float*)d_in[24];
    float* out = (float*)d_out;

    img_k<<<2048, 256>>>(image_feat, Wb, bb, aiw, aib);
    prep2_k<<<33, 512>>>(aiw, aib, aow, aob);
    tab_k<<<dim3(NTAB / 8, 32), 256>>>();

    pack_wih_k<<<6144, 128>>>(W_ih);

    float* Pclass; cudaGetSymbolAddress((void**)&Pclass, g_Pclass);
    float* Pbin;   cudaGetSymbolAddress((void**)&Pbin, g_Pbin);
    float* Wihb;   cudaGetSymbolAddress((void**)&Wihb, g_Wih_bins);
    float* Hall;   cudaGetSymbolAddress((void**)&Hall, g_Hall);
    float* Wcat;   cudaGetSymbolAddress((void**)&Wcat, g_Wcat);
    float* bcat;   cudaGetSymbolAddress((void**)&bcat, g_bcat);
    float* Chead;  cudaGetSymbolAddress((void**)&Chead, g_Chead);

    // class table: Pclass = class_emb @ W_ih_block0^T
    sgemm_nt<<<dim3(24, 1), 256>>>(class_emb, 512, W_ih + 0, 2560, nullptr,
                                   Pclass, 1536, NCP, 1536, 512);
    // all 4 bin tables in ONE GEMM against packed W_ih bins
    sgemm_nt<<<dim3(96, 2), 256>>>(bin_emb, 512, Wihb, 512, nullptr,
                                   Pbin, 6144, NBP, 6144, 512);

    gather_k<<<T_STEPS * BATCH, 384>>>(b_ih, y_class, y_x, y_y, y_w, y_h);
    pack_k<<<768, 128>>>(Wc, bc, Wp, bp, Wd, bd);

    cudaFuncSetAttribute(scan_k, cudaFuncAttributeMaxDynamicSharedMemorySize,
                         SM_TOT * sizeof(float));
    scan_k<<<NBLK, 128, SM_TOT * sizeof(float)>>>(W_hh, b_hh, aiw, aib, aow, aob);

    // heads: Chead = Hall(3072x512) @ Wcat(768x512)^T + bcat
    sgemm_nt<<<dim3(12, 24), 256>>>(Hall, 512, Wcat, 512, bcat, Chead, 768, 3072, 768, 512);

    scatter_k<<<T_STEPS * BATCH, 256>>>(out);
}

// round 16
// speedup vs baseline: 2.8314x; 1.0706x over previous
#include <cuda_runtime.h>
#include <cstdint>

#define T_STEPS 96
#define BATCH   32
#define HDIM    512
#define NCP     82
#define NBP     226
#define FEAT    2048
#define NBLK    128
#define NTAB    2048
#define LOG2E   1.4426950408889634f

#define OFF_OC 0u
#define OFF_OX 251904u
#define OFF_OY 946176u
#define OFF_OW 1640448u
#define OFF_OH 2334720u
#define OFF_OD 3028992u

typedef unsigned long long ull;

// ---- static device scratch (no runtime allocation) ----
__device__ __align__(128) float g_k[BATCH * HDIM];
__device__ __align__(128) float g_v[BATCH * HDIM];
__device__ __align__(128) float g_kmin[BATCH];
__device__ __align__(128) float g_kmax[BATCH];
__device__ __align__(128) float g_qlo[BATCH];
__device__ __align__(128) float g_qstep[BATCH];
__device__ __align__(128) float g_qinv[BATCH];
__device__ __align__(128) float g_tab[(size_t)BATCH * NTAB * 8];
__device__ __align__(128) float g_Pclass[NCP * 1536];
__device__ __align__(128) float g_Wih_bins[6144 * 512];
__device__ __align__(128) float g_Pbin[(size_t)NBP * 6144];
__device__ __align__(128) float g_gi[(size_t)T_STEPS * BATCH * 1536];
__device__ __align__(128) float g_h[2 * BATCH * HDIM];
__device__ __align__(128) float g_Hall[(size_t)T_STEPS * BATCH * HDIM];
__device__ __align__(128) float g_Wcat[768 * 512];
__device__ __align__(128) float g_bcat[768];
__device__ __align__(128) float g_Chead[(size_t)3072 * 768];
__device__ unsigned g_bar;
__device__ unsigned g_snap;

__device__ __forceinline__ float ex2f(float x) {
    float y; asm("ex2.approx.ftz.f32 %0, %1;" : "=f"(y) : "f"(x)); return y;
}
__device__ __forceinline__ float sigmf(float x) {
    return 1.f / (1.f + ex2f(-x * LOG2E));
}
__device__ __forceinline__ float tanhf_f(float x) {
    x = fminf(fmaxf(x, -15.f), 15.f);
    float e = ex2f(-2.f * x * LOG2E);
    return (1.f - e) / (1.f + e);
}
__device__ __forceinline__ float4 add4(float4 a, const float* p) {
    float4 b = *(const float4*)p;
    a.x += b.x; a.y += b.y; a.z += b.z; a.w += b.w; return a;
}

// packed f32x2 FMA: d = a*b + c (element-wise on 2 packed floats)
#define FMA2(d, a, b, c) \
    asm("fma.rn.f32x2 %0, %1, %2, %3;" : "=l"(d) : "l"(a), "l"(b), "l"(c))
__device__ __forceinline__ float ulo(ull v) { return __uint_as_float((unsigned)v); }
__device__ __forceinline__ float uhi(ull v) { return __uint_as_float((unsigned)(v >> 32)); }

// ---- img = x@Wb.T+bb -> k,v (one warp per output) ----
__global__ __launch_bounds__(256) void img_k(
    const float* __restrict__ xf, const float* __restrict__ Wb,
    const float* __restrict__ bb, const float* __restrict__ aiw,
    const float* __restrict__ aib)
{
    int gw = blockIdx.x * 8 + (threadIdx.x >> 5);
    int lane = threadIdx.x & 31;
    int b = gw >> 9, i = gw & 511;
    const float4* xr = (const float4*)(xf + (size_t)b * FEAT);
    const float4* wr = (const float4*)(Wb + (size_t)i * FEAT);
    float acc = 0.f;
#pragma unroll 4
    for (int m = 0; m < 16; ++m) {
        float4 a = xr[m * 32 + lane];
        float4 w = wr[m * 32 + lane];
        acc = fmaf(a.x, w.x, acc); acc = fmaf(a.y, w.y, acc);
        acc = fmaf(a.z, w.z, acc); acc = fmaf(a.w, w.w, acc);
    }
    for (int d = 16; d; d >>= 1) acc += __shfl_down_sync(0xffffffffu, acc, d);
    if (lane == 0) {
        acc += bb[i];
        g_k[b * 512 + i] = fmaf(acc, aiw[1], aib[1]);
        g_v[b * 512 + i] = fmaf(acc, aiw[2], aib[2]);
    }
}

// ---- pack W_ih bin blocks into contiguous [4*1536, 512] ----
__global__ __launch_bounds__(128) void pack_wih_k(const float* __restrict__ W_ih)
{
    int r = blockIdx.x;
    int s = r / 1536;
    int g = r - s * 1536;
    int f = threadIdx.x << 2;
    float4 v = *(const float4*)(W_ih + (size_t)g * 2560 + 512 * (s + 1) + f);
    *(float4*)(g_Wih_bins + (size_t)r * 512 + f) = v;
}

// ---- per-batch k/v extrema, q-range, h0=0, barrier snapshot ----
__global__ __launch_bounds__(512) void prep2_k(
    const float* __restrict__ aiw, const float* __restrict__ aib,
    const float* __restrict__ aow, const float* __restrict__ aob)
{
    int blk = blockIdx.x, tid = threadIdx.x;
    if (blk < 32) {
        float kv = g_k[blk * 512 + tid], vv = g_v[blk * 512 + tid];
        float kmn = kv, kmx = kv, vmn = vv, vmx = vv;
        for (int d = 16; d; d >>= 1) {
            kmn = fminf(kmn, __shfl_xor_sync(0xffffffffu, kmn, d));
            kmx = fmaxf(kmx, __shfl_xor_sync(0xffffffffu, kmx, d));
            vmn = fminf(vmn, __shfl_xor_sync(0xffffffffu, vmn, d));
            vmx = fmaxf(vmx, __shfl_xor_sync(0xffffffffu, vmx, d));
        }
        __shared__ float s4[4][16];
        if ((tid & 31) == 0) {
            s4[0][tid >> 5] = kmn; s4[1][tid >> 5] = kmx;
            s4[2][tid >> 5] = vmn; s4[3][tid >> 5] = vmx;
        }
        __syncthreads();
        if (tid == 0) {
            for (int w = 1; w < 16; ++w) {
                kmn = fminf(kmn, s4[0][w]); kmx = fmaxf(kmx, s4[1][w]);
                vmn = fminf(vmn, s4[2][w]); vmx = fmaxf(vmx, s4[3][w]);
            }
            g_kmin[blk] = kmn; g_kmax[blk] = kmx;
            float ow = aow[0], ob = aob[0];
            float ca = fminf(ow * vmn, ow * vmx) + ob;
            float cb = fmaxf(ow * vmn, ow * vmx) + ob;
            float lo = fminf(-1.f, ca), hi = fmaxf(1.f, cb);
            float aw = aiw[0], ab = aib[0];
            float q1 = fmaf(aw, lo, ab), q2 = fmaf(aw, hi, ab);
            float qlo = fminf(q1, q2), qhi = fmaxf(q1, q2);
            float rng = fmaxf(qhi - qlo, 1e-3f);
            qlo -= 0.002f * rng; qhi += 0.002f * rng; rng = qhi - qlo;
            g_qlo[blk] = qlo;
            g_qstep[blk] = rng / (float)(NTAB - 1);
            g_qinv[blk] = (float)(NTAB - 1) / rng;
        }
    } else {
        for (int idx = tid; idx < BATCH * HDIM; idx += 512) g_h[idx] = 0.f;
        if (tid == 0) g_snap = g_bar;
    }
}

// ---- build per-batch rank-1 softmax moment table ----
__global__ __launch_bounds__(256) void tab_k()
{
    int warp = threadIdx.x >> 5, lane = threadIdx.x & 31;
    int idx = blockIdx.x * 8 + warp;
    int b = blockIdx.y;
    float qlo = g_qlo[b], step = g_qstep[b];
    float q0 = fmaf((float)idx, step, qlo);
    float M = (q0 >= 0.f) ? q0 * g_kmax[b] : q0 * g_kmin[b];
    float s0 = 0.f, s1 = 0.f, s2 = 0.f, s3 = 0.f;
    float w0 = 0.f, w1 = 0.f, w2 = 0.f, w3 = 0.f;
    const float* kp = g_k + b * 512;
    const float* vp = g_v + b * 512;
#pragma unroll 4
    for (int jj = 0; jj < 16; ++jj) {
        int j = jj * 32 + lane;
        float k = kp[j], v = vp[j];
        float t = ex2f(fmaf(q0, k, -M) * LOG2E);
        float tk = t * k, tk2 = tk * k, tk3 = tk2 * k;
        s0 += t; s1 += tk; s2 += tk2; s3 += tk3;
        w0 = fmaf(t, v, w0); w1 = fmaf(tk, v, w1);
        w2 = fmaf(tk2, v, w2); w3 = fmaf(tk3, v, w3);
    }
#pragma unroll
    for (int d = 16; d; d >>= 1) {
        s0 += __shfl_xor_sync(0xffffffffu, s0, d);
        s1 += __shfl_xor_sync(0xffffffffu, s1, d);
        s2 += __shfl_xor_sync(0xffffffffu, s2, d);
        s3 += __shfl_xor_sync(0xffffffffu, s3, d);
        w0 += __shfl_xor_sync(0xffffffffu, w0, d);
        w1 += __shfl_xor_sync(0xffffffffu, w1, d);
        w2 += __shfl_xor_sync(0xffffffffu, w2, d);
        w3 += __shfl_xor_sync(0xffffffffu, w3, d);
    }
    if (lane == 0) {
        float* o = g_tab + (((size_t)b * NTAB + idx) << 3);
        *(float4*)o       = make_float4(s0, s1, s2 * 0.5f, s3 * (1.f / 6.f));
        *(float4*)(o + 4) = make_float4(w0, w1, w2 * 0.5f, w3 * (1.f / 6.f));
    }
}

// ---- generic SGEMM: C[M,N] = A[M,K]@B[N,K]^T (+bias), BM128/BN64/BK16 ----
__global__ __launch_bounds__(256) void sgemm_nt(
    const float* __restrict__ A, int lda,
    const float* __restrict__ B, int ldb,
    const float* __restrict__ bias,
    float* __restrict__ C, int ldc, int M, int N, int K)
{
    __shared__ float As[16 * 132];
    __shared__ float Bs[16 * 68];
    int tid = threadIdx.x;
    int bm = blockIdx.y * 128, bn = blockIdx.x * 64;
    int tx = tid & 15, ty = tid >> 4;
    float acc[8][4];
#pragma unroll
    for (int i = 0; i < 8; ++i)
#pragma unroll
        for (int j = 0; j < 4; ++j) acc[i][j] = 0.f;
    int lr = tid >> 2, lk = (tid & 3) << 2;

    for (int kt = 0; kt < K; kt += 16) {
        float4 a0 = make_float4(0.f, 0.f, 0.f, 0.f), a1 = a0;
        int r0 = bm + lr, r1 = r0 + 64;
        if (r0 < M) a0 = *(const float4*)(A + (size_t)r0 * lda + kt + lk);
        if (r1 < M) a1 = *(const float4*)(A + (size_t)r1 * lda + kt + lk);
        float4 b0 = *(const float4*)(B + (size_t)(bn + lr) * ldb + kt + lk);
        __syncthreads();
        As[(lk + 0) * 132 + lr] = a0.x; As[(lk + 1) * 132 + lr] = a0.y;
        As[(lk + 2) * 132 + lr] = a0.z; As[(lk + 3) * 132 + lr] = a0.w;
        As[(lk + 0) * 132 + lr + 64] = a1.x; As[(lk + 1) * 132 + lr + 64] = a1.y;
        As[(lk + 2) * 132 + lr + 64] = a1.z; As[(lk + 3) * 132 + lr + 64] = a1.w;
        Bs[(lk + 0) * 68 + lr] = b0.x; Bs[(lk + 1) * 68 + lr] = b0.y;
        Bs[(lk + 2) * 68 + lr] = b0.z; Bs[(lk + 3) * 68 + lr] = b0.w;
        __syncthreads();
#pragma unroll
        for (int kk = 0; kk < 16; ++kk) {
            float ar[8], br[4];
            *(float4*)(ar)     = *(const float4*)&As[kk * 132 + ty * 8];
            *(float4*)(ar + 4) = *(const float4*)&As[kk * 132 + ty * 8 + 4];
            *(float4*)(br)     = *(const float4*)&Bs[kk * 68 + tx * 4];
#pragma unroll
            for (int i = 0; i < 8; ++i)
#pragma unroll
                for (int j = 0; j < 4; ++j)
                    acc[i][j] = fmaf(ar[i], br[j], acc[i][j]);
        }
    }
#pragma unroll
    for (int i = 0; i < 8; ++i) {
        int r = bm + ty * 8 + i;
        if (r < M) {
#pragma unroll
            for (int j = 0; j < 4; ++j) {
                int n = bn + tx * 4 + j;
                float v = acc[i][j];
                if (bias) v += bias[n];
                C[(size_t)r * ldc + n] = v;
            }
        }
    }
}

// ---- gi[t,b] = b_ih + Pclass[c] + sum Pbin_s[idx] ----
__global__ __launch_bounds__(384) void gather_k(
    const float* __restrict__ b_ih, const int* __restrict__ yc,
    const int* __restrict__ yx, const int* __restrict__ yy,
    const int* __restrict__ yw, const int* __restrict__ yh)
{
    int row = blockIdx.x;
    int t = row >> 5, b = row & 31;
    int c = 0, xi = 0, yi = 0, wi = 0, hi = 0;
    if (t > 0) {
        int o = b * T_STEPS + t - 1;
        c = yc[o]; xi = yx[o]; yi = yy[o]; wi = yw[o]; hi = yh[o];
    }
    int f = threadIdx.x << 2;
    float4 v = *(const float4*)(b_ih + f);
    v = add4(v, g_Pclass + (size_t)c * 1536 + f);
    v = add4(v, g_Pbin + (size_t)xi * 6144 + 0    + f);
    v = add4(v, g_Pbin + (size_t)yi * 6144 + 1536 + f);
    v = add4(v, g_Pbin + (size_t)wi * 6144 + 3072 + f);
    v = add4(v, g_Pbin + (size_t)hi * 6144 + 4608 + f);
    *(float4*)(g_gi + (size_t)row * 1536 + f) = v;
}

// ---- pack head weights: Wc | Wp[0:452) | Wp[678:904) | Wd | zeros ----
__global__ __launch_bounds__(128) void pack_k(
    const float* __restrict__ Wc, const float* __restrict__ bc,
    const float* __restrict__ Wp, const float* __restrict__ bp,
    const float* __restrict__ Wd, const float* __restrict__ bd)
{
    int r = blockIdx.x;
    const float* src = nullptr; float bv = 0.f;
    if (r < 82)       { src = Wc + (size_t)r * 512;         bv = bc[r]; }
    else if (r < 534) { src = Wp + (size_t)(r - 82) * 512;  bv = bp[r - 82]; }
    else if (r < 760) { src = Wp + (size_t)(r + 144) * 512; bv = bp[r + 144]; }
    else if (r < 763) { src = Wd + (size_t)(r - 760) * 512; bv = bd[r - 760]; }
    int f = threadIdx.x << 2;
    float4 v = src ? *(const float4*)(src + f) : make_float4(0.f, 0.f, 0.f, 0.f);
    *(float4*)(g_Wcat + (size_t)r * 512 + f) = v;
    if (threadIdx.x == 0) g_bcat[r] = bv;
}

// ---- persistent scan kernel: 128 blocks x 128 threads ----
#define SM_H   0          /* 512 * 36 = 18432 */
#define SM_WD  18432      /* 12 rows x 512 x 2 (duplicated pairs) = 12288 */
#define SM_BH  30720      /* 12 */
#define SM_QL  30732
#define SM_QS  30764
#define SM_QI  30796
#define SM_TOT 30828      /* floats -> 123312 bytes */

__global__ void __launch_bounds__(128, 1) scan_k(
    const float* __restrict__ W_hh, const float* __restrict__ b_hh,
    const float* __restrict__ aiw, const float* __restrict__ aib,
    const float* __restrict__ aow, const float* __restrict__ aob)
{
    extern __shared__ float sm[];
    const int tid = threadIdx.x;
    const int i0 = blockIdx.x * 4;
    const float aw0 = aiw[0], ab0 = aib[0];
    const float ow = aow[0], ob = aob[0];
    const unsigned snap = *(volatile unsigned*)&g_snap;

    // W_hh slice, duplicated into (w,w) pairs for FFMA2
    for (int idx = tid; idx < 6144; idx += 128) {
        int lr = idx >> 9, k = idx & 511;   // lr = gate*4 + ii
        float w = W_hh[(size_t)((lr >> 2) * 512 + i0 + (lr & 3)) * 512 + k];
        sm[SM_WD + lr * 1024 + 2 * k]     = w;
        sm[SM_WD + lr * 1024 + 2 * k + 1] = w;
    }
    if (tid < 12) sm[SM_BH + tid] = b_hh[(tid >> 2) * 512 + i0 + (tid & 3)];
    if (tid < 32) {
        sm[SM_QL + tid] = g_qlo[tid];
        sm[SM_QS + tid] = g_qstep[tid];
        sm[SM_QI + tid] = g_qinv[tid];
    }
    __syncthreads();

    // lane map: bg in LOW 3 bits -> conflict-free h LDS + broadcast w LDS
    const int ii = tid >> 5;          // 0..3 (warp id)
    const int ks = (tid >> 3) & 3;    // k-split (lane bits 3,4)
    const int bg = tid & 7;           // batch quad
    const int bsel = (bg << 2) | ks;  // this lane's batch after reduce

    for (int t = 0; t < T_STEPS; ++t) {
        // prefetch gi (independent of h; hides under h exchange)
        const float* gp = g_gi + ((size_t)((t << 5) | bsel)) * 1536 + i0 + ii;
        float gir = __ldg(gp), giz = __ldg(gp + 512), gin = __ldg(gp + 1024);

        // load h_prev (written by other SMs) -> smem, stride-36 layout
        const float4* hsrc = (const float4*)(g_h + (t & 1) * 16384);
#pragma unroll 8
        for (int r = 0; r < 32; ++r) {
            int i4 = r * 128 + tid;
            float4 hv = __ldcg(hsrc + i4);
            int k = i4 >> 3, b0 = (i4 & 7) << 2;
            *(float4*)&sm[SM_H + k * 36 + b0] = hv;
        }
        __syncthreads();

        // gh = W_hh_slice @ h via packed f32x2 FMA
        ull acc[6] = {0ull, 0ull, 0ull, 0ull, 0ull, 0ull};
        const float* wd = &sm[SM_WD + ii * 1024];
#pragma unroll 4
        for (int m = 0; m < 128; ++m) {
            int k = (m << 2) | ks;
            ulonglong2 h2 = *(const ulonglong2*)&sm[SM_H + k * 36 + (bg << 2)];
            ull w0 = *(const ull*)(wd + 2 * k);
            ull w1 = *(const ull*)(wd + 4096 + 2 * k);
            ull w2 = *(const ull*)(wd + 8192 + 2 * k);
            FMA2(acc[0], w0, h2.x, acc[0]); FMA2(acc[1], w0, h2.y, acc[1]);
            FMA2(acc[2], w1, h2.x, acc[2]); FMA2(acc[3], w1, h2.y, acc[3]);
            FMA2(acc[4], w2, h2.x, acc[4]); FMA2(acc[5], w2, h2.y, acc[5]);
        }
        float a0[4], a1[4], a2[4];
        a0[0] = ulo(acc[0]); a0[1] = uhi(acc[0]); a0[2] = ulo(acc[1]); a0[3] = uhi(acc[1]);
        a1[0] = ulo(acc[2]); a1[1] = uhi(acc[2]); a1[2] = ulo(acc[3]); a1[3] = uhi(acc[3]);
        a2[0] = ulo(acc[4]); a2[1] = uhi(acc[4]); a2[2] = ulo(acc[5]); a2[3] = uhi(acc[5]);
#pragma unroll
        for (int j = 0; j < 4; ++j) {
            a0[j] += __shfl_xor_sync(0xffffffffu, a0[j], 8);
            a0[j] += __shfl_xor_sync(0xffffffffu, a0[j], 16);
            a1[j] += __shfl_xor_sync(0xffffffffu, a1[j], 8);
            a1[j] += __shfl_xor_sync(0xffffffffu, a1[j], 16);
            a2[j] += __shfl_xor_sync(0xffffffffu, a2[j], 8);
            a2[j] += __shfl_xor_sync(0xffffffffu, a2[j], 16);
        }
        float ghr = a0[ks] + sm[SM_BH + ii];
        float ghz = a1[ks] + sm[SM_BH + 4 + ii];
        float ghn = a2[ks] + sm[SM_BH + 8 + ii];
        float r_ = sigmf(gir + ghr);
        float z_ = sigmf(giz + ghz);
        float n_ = tanhf_f(fmaf(r_, ghn, gin));
        float hp = sm[SM_H + (i0 + ii) * 36 + bsel];
        float hg = fmaf(1.f - z_, n_, z_ * hp);

        // rank-1 attention via cubic moment table: ctx = W(dq)/S(dq)
        float q = fmaf(hg, aw0, ab0);
        float qlo = sm[SM_QL + bsel];
        float u = (q - qlo) * sm[SM_QI + bsel];
        u = fminf(fmaxf(u, 0.f), (float)(NTAB - 1));
        int idx = (int)(u + 0.5f);
        float dq = q - fmaf((float)idx, sm[SM_QS + bsel], qlo);
        const float4* tp = (const float4*)(g_tab + (((size_t)bsel * NTAB + idx) << 3));
        float4 S = __ldg(tp);
        float4 Wm = __ldg(tp + 1);
        float den = fmaf(dq, fmaf(dq, fmaf(dq, S.w, S.z), S.y), S.x);
        float num = fmaf(dq, fmaf(dq, fmaf(dq, Wm.w, Wm.z), Wm.y), Wm.x);
        float hatt = fmaf(__fdividef(num, den), ow, ob);

        g_Hall[(size_t)((t << 5) | bsel) * 512 + i0 + ii] = hatt;
        if (t != T_STEPS - 1) {
            __stcg(&g_h[((t + 1) & 1) * 16384 + ((i0 + ii) << 5) + bsel], hatt);
            __syncthreads();
            if (tid == 0) {
                __threadfence();
                atomicAdd(&g_bar, 1u);
                unsigned target = snap + (unsigned)(t + 1) * NBLK;
                while ((int)(*(volatile unsigned*)&g_bar - target) < 0) { }
            }
            __syncthreads();
        }
    }
}

// ---- scatter heads to output (T,B)->(B,T), zero oh ----
__global__ __launch_bounds__(256) void scatter_k(float* __restrict__ out)
{
    int row = blockIdx.x;              // t*32 + b
    int t = row >> 5, b = row & 31;
    const float* src = g_Chead + (size_t)row * 768;
    int bt = b * 96 + t;
    for (int n = threadIdx.x; n < 226; n += 256) {
        if (n < 82) out[OFF_OC + (size_t)bt * 82 + n] = src[n];
        out[OFF_OX + (size_t)bt * 226 + n] = src[82 + n];
        out[OFF_OY + (size_t)bt * 226 + n] = src[308 + n];
        out[OFF_OW + (size_t)bt * 226 + n] = src[534 + n];
        out[OFF_OH + (size_t)bt * 226 + n] = 0.f;
        if (n < 3) out[OFF_OD + (size_t)bt * 3 + n] = src[760 + n];
    }
}

extern "C" void kernel_launch(void* const* d_in, const int* in_sizes, int n_in,
                              void* d_out, int out_size)
{
    const float* image_feat = (const float*)d_in[0];
    const int*   y_class    = (const int*)d_in[1];
    const int*   y_x        = (const int*)d_in[2];
    const int*   y_y        = (const int*)d_in[3];
    const int*   y_w        = (const int*)d_in[4];
    const int*   y_h        = (const int*)d_in[5];
    const float* class_emb  = (const float*)d_in[7];
    const float* bin_emb    = (const float*)d_in[8];
    const float* Wb         = (const float*)d_in[9];
    const float* bb         = (const float*)d_in[10];
    const float* W_ih       = (const float*)d_in[11];
    const float* b_ih       = (const float*)d_in[12];
    const float* W_hh       = (const float*)d_in[13];
    const float* b_hh       = (const float*)d_in[14];
    const float* aiw        = (const float*)d_in[15];
    const float* aib        = (const float*)d_in[16];
    const float* aow        = (const float*)d_in[17];
    const float* aob        = (const float*)d_in[18];
    const float* Wc         = (const float*)d_in[19];
    const float* bc         = (const float*)d_in[20];
    const float* Wp         = (const float*)d_in[21];
    const float* bp         = (const float*)d_in[22];
    const float* Wd         = (const float*)d_in[23];
    const float* bd         = (const float*)d_in[24];
    float* out = (float*)d_out;

    // lazily created side streams/events (host objects; reused across calls)
    static cudaStream_t s1 = nullptr, s2 = nullptr;
    static cudaEvent_t e0 = nullptr, eA = nullptr, eB = nullptr;
    if (!s1) {
        cudaStreamCreateWithFlags(&s1, cudaStreamNonBlocking);
        cudaStreamCreateWithFlags(&s2, cudaStreamNonBlocking);
        cudaEventCreateWithFlags(&e0, cudaEventDisableTiming);
        cudaEventCreateWithFlags(&eA, cudaEventDisableTiming);
        cudaEventCreateWithFlags(&eB, cudaEventDisableTiming);
    }

    float* Pclass; cudaGetSymbolAddress((void**)&Pclass, g_Pclass);
    float* Pbin;   cudaGetSymbolAddress((void**)&Pbin, g_Pbin);
    float* Wihb;   cudaGetSymbolAddress((void**)&Wihb, g_Wih_bins);
    float* Hall;   cudaGetSymbolAddress((void**)&Hall, g_Hall);
    float* Wcat;   cudaGetSymbolAddress((void**)&Wcat, g_Wcat);
    float* bcat;   cudaGetSymbolAddress((void**)&bcat, g_bcat);
    float* Chead;  cudaGetSymbolAddress((void**)&Chead, g_Chead);

    // fork side streams off the (capturing) main stream
    cudaEventRecord(e0, 0);
    cudaStreamWaitEvent(s1, e0, 0);
    cudaStreamWaitEvent(s2, e0, 0);

    // side stream 1: attention constant pipeline
    img_k<<<2048, 256, 0, s1>>>(image_feat, Wb, bb, aiw, aib);
    prep2_k<<<33, 512, 0, s1>>>(aiw, aib, aow, aob);
    tab_k<<<dim3(NTAB / 8, 32), 256, 0, s1>>>();
    cudaEventRecord(eA, s1);

    // side stream 2: class table + head weight pack
    sgemm_nt<<<dim3(24, 1), 256, 0, s2>>>(class_emb, 512, W_ih + 0, 2560, nullptr,
                                          Pclass, 1536, NCP, 1536, 512);
    pack_k<<<768, 128, 0, s2>>>(Wc, bc, Wp, bp, Wd, bd);
    cudaEventRecord(eB, s2);

    // main stream: critical chain
    pack_wih_k<<<6144, 128>>>(W_ih);
    sgemm_nt<<<dim3(96, 2), 256>>>(bin_emb, 512, Wihb, 512, nullptr,
                                   Pbin, 6144, NBP, 6144, 512);
    cudaStreamWaitEvent(0, eB, 0);   // need Pclass (and pack_k joins here too)
    gather_k<<<T_STEPS * BATCH, 384>>>(b_ih, y_class, y_x, y_y, y_w, y_h);
    cudaStreamWaitEvent(0, eA, 0);   // need k/v extrema, tab, h0, snap

    cudaFuncSetAttribute(scan_k, cudaFuncAttributeMaxDynamicSharedMemorySize,
                         SM_TOT * sizeof(float));
    scan_k<<<NBLK, 128, SM_TOT * sizeof(float)>>>(W_hh, b_hh, aiw, aib, aow, aob);

    // heads: Chead = Hall(3072x512) @ Wcat(768x512)^T + bcat
    sgemm_nt<<<dim3(12, 24), 256>>>(Hall, 512, Wcat, 512, bcat, Chead, 768, 3072, 768, 512);

    scatter_k<<<T_STEPS * BATCH, 256>>>(out);
}